// round 13
// baseline (speedup 1.0000x reference)
#include <cuda_runtime.h>
#include <math.h>

#define NN 4096
#define KK 4
#define FPD 64
#define KFP 256
#define MAXDEG 128

// ---------------- scratch (static device globals; no runtime alloc) ----------
__device__ float  g_xproj[NN * KFP];      // 4 MB
__device__ float  g_src[NN * KK];
__device__ float  g_tgt[NN * KK];
__device__ double g_sum, g_sumsq;
__device__ float  g_mean, g_invstd;
__device__ int    g_nbr[NN * MAXDEG];     // 2 MB
__device__ int    g_cnt[NN];

// ---------------- 0: zero the stats accumulators -----------------------------
__global__ void k_zero() {
    if (threadIdx.x == 0) { g_sum = 0.0; g_sumsq = 0.0; }
}

// ---------------- 1: x_proj = x @ W + b  (4096x256 @ 256x256, fp32) ----------
// 64x64 block tile, BK=16, 256 threads, 4x4 micro-tile per thread.
__global__ void __launch_bounds__(256) k_gemm(const float* __restrict__ x,
                                              const float* __restrict__ W,
                                              const float* __restrict__ bias) {
    __shared__ float As[16][64];
    __shared__ float Bs[16][64];
    const int tid = threadIdx.x;
    const int rowBase = blockIdx.x * 64;
    const int colBase = blockIdx.y * 64;
    const int tx = tid & 15, ty = tid >> 4;

    float acc[4][4] = {};

    for (int kt = 0; kt < 256; kt += 16) {
        // load A tile (64 rows x 16 k) transposed into As[k][row]
        {
            int r = tid >> 2, c4 = tid & 3;
            float4 v = *(const float4*)(x + (size_t)(rowBase + r) * 256 + kt + c4 * 4);
            As[c4 * 4 + 0][r] = v.x;
            As[c4 * 4 + 1][r] = v.y;
            As[c4 * 4 + 2][r] = v.z;
            As[c4 * 4 + 3][r] = v.w;
        }
        // load B tile (16 k x 64 cols)
        {
            int r = tid >> 4, c4 = tid & 15;
            *(float4*)&Bs[r][c4 * 4] =
                *(const float4*)(W + (size_t)(kt + r) * 256 + colBase + c4 * 4);
        }
        __syncthreads();
        #pragma unroll
        for (int k = 0; k < 16; k++) {
            float4 a = *(const float4*)&As[k][ty * 4];
            float4 b = *(const float4*)&Bs[k][tx * 4];
            float av[4] = {a.x, a.y, a.z, a.w};
            float bv[4] = {b.x, b.y, b.z, b.w};
            #pragma unroll
            for (int i = 0; i < 4; i++)
                #pragma unroll
                for (int j = 0; j < 4; j++)
                    acc[i][j] = fmaf(av[i], bv[j], acc[i][j]);
        }
        __syncthreads();
    }

    float b0 = bias[colBase + tx * 4 + 0];
    float b1 = bias[colBase + tx * 4 + 1];
    float b2 = bias[colBase + tx * 4 + 2];
    float b3 = bias[colBase + tx * 4 + 3];
    #pragma unroll
    for (int i = 0; i < 4; i++) {
        int row = rowBase + ty * 4 + i;
        float4 o;
        o.x = acc[i][0] + b0;
        o.y = acc[i][1] + b1;
        o.z = acc[i][2] + b2;
        o.w = acc[i][3] + b3;
        *(float4*)(g_xproj + (size_t)row * 256 + colBase + tx * 4) = o;
    }
}

// ---------------- 2: src/tgt attention dots  (one warp per (n,k)) ------------
__global__ void __launch_bounds__(256) k_score(const float* __restrict__ a_left,
                                               const float* __restrict__ a_right) {
    int gw   = blockIdx.x * 8 + (threadIdx.x >> 5);  // 0 .. N*K-1
    int lane = threadIdx.x & 31;
    int n = gw >> 2, k = gw & 3;
    const float* xp = g_xproj + (size_t)n * 256 + k * 64;
    float s = 0.f, t = 0.f;
    #pragma unroll
    for (int u = 0; u < 2; u++) {
        float v = xp[lane + u * 32];
        s = fmaf(v, a_left [k * 64 + lane + u * 32], s);
        t = fmaf(v, a_right[k * 64 + lane + u * 32], t);
    }
    #pragma unroll
    for (int o = 16; o; o >>= 1) {
        s += __shfl_xor_sync(0xffffffffu, s, o);
        t += __shfl_xor_sync(0xffffffffu, t, o);
    }
    if (lane == 0) { g_src[n * 4 + k] = s; g_tgt[n * 4 + k] = t; }
}

// ---------------- 3: global mean/std of leaky(src_i + tgt_j) streaming -------
// grid (16 i-blocks, 4 k, 4 j-chunks); each thread: 1 src value vs 1024 tgt.
__global__ void __launch_bounds__(256) k_stats() {
    __shared__ float ts[1024];
    __shared__ double wsum[8], wsq[8];
    const int k  = blockIdx.y;
    const int j0 = blockIdx.z * 1024;
    for (int u = threadIdx.x; u < 1024; u += 256)
        ts[u] = g_tgt[(size_t)(j0 + u) * 4 + k];
    __syncthreads();

    const int i = blockIdx.x * 256 + threadIdx.x;
    const float s = g_src[(size_t)i * 4 + k];
    float sum = 0.f, sq = 0.f;
    #pragma unroll 8
    for (int u = 0; u < 1024; u++) {
        float z = s + ts[u];
        float l = fmaxf(z, 0.2f * z);   // leaky_relu, slope 0.2
        sum += l;
        sq = fmaf(l, l, sq);
    }
    #pragma unroll
    for (int o = 16; o; o >>= 1) {
        sum += __shfl_xor_sync(0xffffffffu, sum, o);
        sq  += __shfl_xor_sync(0xffffffffu, sq,  o);
    }
    int w = threadIdx.x >> 5;
    if ((threadIdx.x & 31) == 0) { wsum[w] = (double)sum; wsq[w] = (double)sq; }
    __syncthreads();
    if (threadIdx.x == 0) {
        double a = 0.0, c = 0.0;
        #pragma unroll
        for (int u = 0; u < 8; u++) { a += wsum[u]; c += wsq[u]; }
        atomicAdd(&g_sum, a);
        atomicAdd(&g_sumsq, c);
    }
}

// ---------------- 4: finalize mean / inv_std (ddof=1) ------------------------
__global__ void k_final() {
    const double M = (double)NN * (double)NN * (double)KK;
    double mean = g_sum / M;
    double var  = (g_sumsq - g_sum * g_sum / M) / (M - 1.0);
    g_mean   = (float)mean;
    g_invstd = (float)(1.0 / sqrt(var));
}

// ---------------- 5: build neighbor lists from dense mask (one warp/row) -----
__global__ void __launch_bounds__(256) k_csr(const float* __restrict__ mask) {
    int row  = blockIdx.x * 8 + (threadIdx.x >> 5);
    int lane = threadIdx.x & 31;
    const float* mrow = mask + (size_t)row * NN;
    int* out = g_nbr + (size_t)row * MAXDEG;
    int cnt = 0;
    for (int base = 0; base < NN; base += 32) {
        float v = mrow[base + lane];
        unsigned bal = __ballot_sync(0xffffffffu, v != 0.0f);
        if (v != 0.0f) {
            int pos = cnt + __popc(bal & ((1u << lane) - 1u));
            if (pos < MAXDEG) out[pos] = base + lane;
        }
        cnt += __popc(bal);
    }
    if (lane == 0) g_cnt[row] = min(cnt, MAXDEG);
}

// ---------------- 6: sparse softmax + gather + ELU (one block per node) ------
__global__ void __launch_bounds__(256) k_agg(float* __restrict__ out) {
    __shared__ float ew[KK][MAXDEG];
    __shared__ int   nb[MAXDEG];
    __shared__ float dinv[KK];

    const int i   = blockIdx.x;
    const int tid = threadIdx.x;
    const int cnt = g_cnt[i];
    const float mean = g_mean, invstd = g_invstd;

    if (tid < cnt) {
        int j = g_nbr[(size_t)i * MAXDEG + tid];
        nb[tid] = j;
        #pragma unroll
        for (int k = 0; k < 4; k++) {
            float z = g_src[(size_t)i * 4 + k] + g_tgt[(size_t)j * 4 + k];
            float l = fmaxf(z, 0.2f * z);
            ew[k][tid] = expf((l - mean) * invstd);
        }
    }
    __syncthreads();
    if (tid < 4) {
        float d = 0.f;
        for (int u = 0; u < cnt; u++) d += ew[tid][u];
        dinv[tid] = 1.0f / d;
    }
    __syncthreads();

    const int k = tid >> 6;
    float acc = 0.f;
    const float* xp = g_xproj + tid;   // column offset, row stride 256
    int u = 0;
    for (; u + 4 <= cnt; u += 4) {
        float w0 = ew[k][u + 0], w1 = ew[k][u + 1];
        float w2 = ew[k][u + 2], w3 = ew[k][u + 3];
        float v0 = xp[(size_t)nb[u + 0] * 256];
        float v1 = xp[(size_t)nb[u + 1] * 256];
        float v2 = xp[(size_t)nb[u + 2] * 256];
        float v3 = xp[(size_t)nb[u + 3] * 256];
        acc = fmaf(w0, v0, acc);
        acc = fmaf(w1, v1, acc);
        acc = fmaf(w2, v2, acc);
        acc = fmaf(w3, v3, acc);
    }
    for (; u < cnt; u++)
        acc = fmaf(ew[k][u], xp[(size_t)nb[u] * 256], acc);

    acc *= dinv[k];
    float h = acc > 0.f ? acc : expm1f(acc);   // ELU (alpha=1)
    out[(size_t)i * 256 + tid] = h;
}

// ---------------- launch ------------------------------------------------------
extern "C" void kernel_launch(void* const* d_in, const int* in_sizes, int n_in,
                              void* d_out, int out_size) {
    const float* x       = (const float*)d_in[0];
    const float* mask    = (const float*)d_in[1];
    // d_in[2] = batch (int32), unused
    const float* W       = (const float*)d_in[3];
    const float* b       = (const float*)d_in[4];
    const float* a_left  = (const float*)d_in[5];
    const float* a_right = (const float*)d_in[6];
    float* out = (float*)d_out;

    k_zero <<<1, 32>>>();
    k_gemm <<<dim3(64, 4), 256>>>(x, W, b);
    k_score<<<2048, 256>>>(a_left, a_right);
    k_stats<<<dim3(16, 4, 4), 256>>>();
    k_final<<<1, 1>>>();
    k_csr  <<<512, 256>>>(mask);
    k_agg  <<<4096, 256>>>(out);
}

// round 16
// speedup vs baseline: 1.0086x; 1.0086x over previous
#include <cuda_runtime.h>
#include <math.h>

#define NN 4096
#define KK 4
#define FPD 64
#define KFP 256
#define MAXDEG 128

// ---------------- scratch (static device globals; no runtime alloc) ----------
__device__ float  g_xproj[NN * KFP];      // 4 MB
__device__ float  g_src[NN * KK];
__device__ float  g_tgt[NN * KK];
__device__ double g_sum, g_sumsq;
__device__ float  g_mean, g_invstd;
__device__ int    g_nbr[NN * MAXDEG];     // 2 MB
__device__ int    g_cnt[NN];

// ---------------- 0: zero the stats accumulators -----------------------------
__global__ void k_zero() {
    if (threadIdx.x == 0) { g_sum = 0.0; g_sumsq = 0.0; }
}

// ---------------- 1: x_proj = x @ W + b  (4096x256 @ 256x256, fp32) ----------
// 64x64 block tile, BK=16, 256 threads, 4x4 micro-tile per thread.
__global__ void __launch_bounds__(256) k_gemm(const float* __restrict__ x,
                                              const float* __restrict__ W,
                                              const float* __restrict__ bias) {
    __shared__ float As[16][64];
    __shared__ float Bs[16][64];
    const int tid = threadIdx.x;
    const int rowBase = blockIdx.x * 64;
    const int colBase = blockIdx.y * 64;
    const int tx = tid & 15, ty = tid >> 4;

    float acc[4][4] = {};

    for (int kt = 0; kt < 256; kt += 16) {
        // load A tile (64 rows x 16 k) transposed into As[k][row]
        {
            int r = tid >> 2, c4 = tid & 3;
            float4 v = *(const float4*)(x + (size_t)(rowBase + r) * 256 + kt + c4 * 4);
            As[c4 * 4 + 0][r] = v.x;
            As[c4 * 4 + 1][r] = v.y;
            As[c4 * 4 + 2][r] = v.z;
            As[c4 * 4 + 3][r] = v.w;
        }
        // load B tile (16 k x 64 cols)
        {
            int r = tid >> 4, c4 = tid & 15;
            *(float4*)&Bs[r][c4 * 4] =
                *(const float4*)(W + (size_t)(kt + r) * 256 + colBase + c4 * 4);
        }
        __syncthreads();
        #pragma unroll
        for (int k = 0; k < 16; k++) {
            float4 a = *(const float4*)&As[k][ty * 4];
            float4 b = *(const float4*)&Bs[k][tx * 4];
            float av[4] = {a.x, a.y, a.z, a.w};
            float bv[4] = {b.x, b.y, b.z, b.w};
            #pragma unroll
            for (int i = 0; i < 4; i++)
                #pragma unroll
                for (int j = 0; j < 4; j++)
                    acc[i][j] = fmaf(av[i], bv[j], acc[i][j]);
        }
        __syncthreads();
    }

    float b0 = bias[colBase + tx * 4 + 0];
    float b1 = bias[colBase + tx * 4 + 1];
    float b2 = bias[colBase + tx * 4 + 2];
    float b3 = bias[colBase + tx * 4 + 3];
    #pragma unroll
    for (int i = 0; i < 4; i++) {
        int row = rowBase + ty * 4 + i;
        float4 o;
        o.x = acc[i][0] + b0;
        o.y = acc[i][1] + b1;
        o.z = acc[i][2] + b2;
        o.w = acc[i][3] + b3;
        *(float4*)(g_xproj + (size_t)row * 256 + colBase + tx * 4) = o;
    }
}

// ---------------- 2: src/tgt attention dots  (one warp per (n,k)) ------------
__global__ void __launch_bounds__(256) k_score(const float* __restrict__ a_left,
                                               const float* __restrict__ a_right) {
    int gw   = blockIdx.x * 8 + (threadIdx.x >> 5);  // 0 .. N*K-1
    int lane = threadIdx.x & 31;
    int n = gw >> 2, k = gw & 3;
    const float* xp = g_xproj + (size_t)n * 256 + k * 64;
    float s = 0.f, t = 0.f;
    #pragma unroll
    for (int u = 0; u < 2; u++) {
        float v = xp[lane + u * 32];
        s = fmaf(v, a_left [k * 64 + lane + u * 32], s);
        t = fmaf(v, a_right[k * 64 + lane + u * 32], t);
    }
    #pragma unroll
    for (int o = 16; o; o >>= 1) {
        s += __shfl_xor_sync(0xffffffffu, s, o);
        t += __shfl_xor_sync(0xffffffffu, t, o);
    }
    if (lane == 0) { g_src[n * 4 + k] = s; g_tgt[n * 4 + k] = t; }
}

// ---------------- 3: global mean/std of leaky(src_i + tgt_j) streaming -------
// grid (16 i-blocks, 4 k, 4 j-chunks); each thread: 1 src value vs 1024 tgt.
__global__ void __launch_bounds__(256) k_stats() {
    __shared__ float ts[1024];
    __shared__ double wsum[8], wsq[8];
    const int k  = blockIdx.y;
    const int j0 = blockIdx.z * 1024;
    for (int u = threadIdx.x; u < 1024; u += 256)
        ts[u] = g_tgt[(size_t)(j0 + u) * 4 + k];
    __syncthreads();

    const int i = blockIdx.x * 256 + threadIdx.x;
    const float s = g_src[(size_t)i * 4 + k];
    float sum = 0.f, sq = 0.f;
    #pragma unroll 8
    for (int u = 0; u < 1024; u++) {
        float z = s + ts[u];
        float l = fmaxf(z, 0.2f * z);   // leaky_relu, slope 0.2
        sum += l;
        sq = fmaf(l, l, sq);
    }
    #pragma unroll
    for (int o = 16; o; o >>= 1) {
        sum += __shfl_xor_sync(0xffffffffu, sum, o);
        sq  += __shfl_xor_sync(0xffffffffu, sq,  o);
    }
    int w = threadIdx.x >> 5;
    if ((threadIdx.x & 31) == 0) { wsum[w] = (double)sum; wsq[w] = (double)sq; }
    __syncthreads();
    if (threadIdx.x == 0) {
        double a = 0.0, c = 0.0;
        #pragma unroll
        for (int u = 0; u < 8; u++) { a += wsum[u]; c += wsq[u]; }
        atomicAdd(&g_sum, a);
        atomicAdd(&g_sumsq, c);
    }
}

// ---------------- 4: finalize mean / inv_std (ddof=1) ------------------------
__global__ void k_final() {
    const double M = (double)NN * (double)NN * (double)KK;
    double mean = g_sum / M;
    double var  = (g_sumsq - g_sum * g_sum / M) / (M - 1.0);
    g_mean   = (float)mean;
    g_invstd = (float)(1.0 / sqrt(var));
}

// ---------------- 5: build neighbor lists from dense mask (one warp/row) -----
__global__ void __launch_bounds__(256) k_csr(const float* __restrict__ mask) {
    int row  = blockIdx.x * 8 + (threadIdx.x >> 5);
    int lane = threadIdx.x & 31;
    const float* mrow = mask + (size_t)row * NN;
    int* out = g_nbr + (size_t)row * MAXDEG;
    int cnt = 0;
    for (int base = 0; base < NN; base += 32) {
        float v = mrow[base + lane];
        unsigned bal = __ballot_sync(0xffffffffu, v != 0.0f);
        if (v != 0.0f) {
            int pos = cnt + __popc(bal & ((1u << lane) - 1u));
            if (pos < MAXDEG) out[pos] = base + lane;
        }
        cnt += __popc(bal);
    }
    if (lane == 0) g_cnt[row] = min(cnt, MAXDEG);
}

// ---------------- 6: sparse softmax + gather + ELU (one block per node) ------
__global__ void __launch_bounds__(256) k_agg(float* __restrict__ out) {
    __shared__ float ew[KK][MAXDEG];
    __shared__ int   nb[MAXDEG];
    __shared__ float dinv[KK];

    const int i   = blockIdx.x;
    const int tid = threadIdx.x;
    const int cnt = g_cnt[i];
    const float mean = g_mean, invstd = g_invstd;

    if (tid < cnt) {
        int j = g_nbr[(size_t)i * MAXDEG + tid];
        nb[tid] = j;
        #pragma unroll
        for (int k = 0; k < 4; k++) {
            float z = g_src[(size_t)i * 4 + k] + g_tgt[(size_t)j * 4 + k];
            float l = fmaxf(z, 0.2f * z);
            ew[k][tid] = expf((l - mean) * invstd);
        }
    }
    __syncthreads();
    if (tid < 4) {
        float d = 0.f;
        for (int u = 0; u < cnt; u++) d += ew[tid][u];
        dinv[tid] = 1.0f / d;
    }
    __syncthreads();

    const int k = tid >> 6;
    float acc = 0.f;
    const float* xp = g_xproj + tid;   // column offset, row stride 256
    int u = 0;
    for (; u + 4 <= cnt; u += 4) {
        float w0 = ew[k][u + 0], w1 = ew[k][u + 1];
        float w2 = ew[k][u + 2], w3 = ew[k][u + 3];
        float v0 = xp[(size_t)nb[u + 0] * 256];
        float v1 = xp[(size_t)nb[u + 1] * 256];
        float v2 = xp[(size_t)nb[u + 2] * 256];
        float v3 = xp[(size_t)nb[u + 3] * 256];
        acc = fmaf(w0, v0, acc);
        acc = fmaf(w1, v1, acc);
        acc = fmaf(w2, v2, acc);
        acc = fmaf(w3, v3, acc);
    }
    for (; u < cnt; u++)
        acc = fmaf(ew[k][u], xp[(size_t)nb[u] * 256], acc);

    acc *= dinv[k];
    float h = acc > 0.f ? acc : expm1f(acc);   // ELU (alpha=1)
    out[(size_t)i * 256 + tid] = h;
}

// ---------------- launch ------------------------------------------------------
extern "C" void kernel_launch(void* const* d_in, const int* in_sizes, int n_in,
                              void* d_out, int out_size) {
    const float* x       = (const float*)d_in[0];
    const float* mask    = (const float*)d_in[1];
    // d_in[2] = batch (int32), unused
    const float* W       = (const float*)d_in[3];
    const float* b       = (const float*)d_in[4];
    const float* a_left  = (const float*)d_in[5];
    const float* a_right = (const float*)d_in[6];
    float* out = (float*)d_out;

    k_zero <<<1, 32>>>();
    k_gemm <<<dim3(64, 4), 256>>>(x, W, b);
    k_score<<<2048, 256>>>(a_left, a_right);
    k_stats<<<dim3(16, 4, 4), 256>>>();
    k_final<<<1, 1>>>();
    k_csr  <<<512, 256>>>(mask);
    k_agg  <<<4096, 256>>>(out);
}